// round 14
// baseline (speedup 1.0000x reference)
#include <cuda_runtime.h>
#include <cstdint>

#define Nn 512
#define Cc 128
#define PP (Nn*Nn)   // 262144 positions

// Scratch (device globals — no allocation allowed in kernel_launch)
__device__ float g_a[(size_t)Cc*PP];     // [c][i][k]  tf32-rounded A operand
__device__ float g_b[(size_t)Cc*PP];     // [c][j][k]  tf32-rounded B operand
__device__ float g_gate[(size_t)PP*Cc];  // [p][c]     sigmoid output gate
__device__ float g_tri[(size_t)Cc*PP];   // [c][i][j]  triangle result

__device__ __forceinline__ float sigmoidf_(float v) {
    return 1.f / (1.f + __expf(-v));
}

// ===================== mma.sync tf32 helpers (sm_80+) ======================
__device__ __forceinline__ uint32_t smem_u32(const void* p) {
    uint32_t a;
    asm("{ .reg .u64 t; cvta.to.shared.u64 t, %1; cvt.u32.u64 %0, t; }"
        : "=r"(a) : "l"(p));
    return a;
}
__device__ __forceinline__ uint32_t cvt_tf32(float f) {
    uint32_t r;
    asm("cvt.rna.tf32.f32 %0, %1;" : "=r"(r) : "f"(f));
    return r;
}
__device__ __forceinline__ float round_tf32(float f) {
    return __uint_as_float(cvt_tf32(f));
}
__device__ __forceinline__ void split_tf32(float f, uint32_t& hi, uint32_t& lo) {
    hi = cvt_tf32(f);
    lo = cvt_tf32(f - __uint_as_float(hi));
}
__device__ __forceinline__ void mma_tf32(float* d, const uint32_t* a, const uint32_t* b) {
    asm volatile(
        "mma.sync.aligned.m16n8k8.row.col.f32.tf32.tf32.f32 "
        "{%0,%1,%2,%3}, {%4,%5,%6,%7}, {%8,%9}, {%0,%1,%2,%3};"
        : "+f"(d[0]), "+f"(d[1]), "+f"(d[2]), "+f"(d[3])
        : "r"(a[0]), "r"(a[1]), "r"(a[2]), "r"(a[3]), "r"(b[0]), "r"(b[1]));
}
__device__ __forceinline__ void ldsm_x4(uint32_t* r, uint32_t addr) {
    asm volatile("ldmatrix.sync.aligned.m8n8.x4.shared.b16 {%0,%1,%2,%3}, [%4];"
        : "=r"(r[0]), "=r"(r[1]), "=r"(r[2]), "=r"(r[3]) : "r"(addr));
}
__device__ __forceinline__ void ldsm_x2(uint32_t* r, uint32_t addr) {
    asm volatile("ldmatrix.sync.aligned.m8n8.x2.shared.b16 {%0,%1}, [%2];"
        : "=r"(r[0]), "=r"(r[1]) : "r"(addr));
}
__device__ __forceinline__ void cp16(uint32_t s, const void* g) {
    asm volatile("cp.async.cg.shared.global [%0], [%1], 16;" :: "r"(s), "l"(g));
}
#define CP_COMMIT() asm volatile("cp.async.commit_group;" ::: "memory")
#define CP_WAIT0()  asm volatile("cp.async.wait_group 0;" ::: "memory")

#define XS 132

// ---------------------------------------------------------------------------
// K1 v7: R13 + manual software-pipelined fragment loads (prefetch ks+1).
// Block = 128 positions, 256 threads (4 pos-warps x 2 d-warps), 2 CTAs/SM.
// ---------------------------------------------------------------------------
__global__ __launch_bounds__(256, 2) void k1_ln_proj(
    const float* __restrict__ x,
    const float* __restrict__ niw, const float* __restrict__ nib,
    const float* __restrict__ giw, const float* __restrict__ piw,
    const float* __restrict__ gow)
{
    extern __shared__ float sm[];
    float* xn = sm;              // [128][132] tf32-rounded LN output
    float* Wg = xn + 128*XS;     // [32][132]
    float* Wp = Wg + 32*XS;      // [32][132]
    float* Wo = Wp + 32*XS;      // [16][132]
    float* ob = Wg;              // pg staging overlay [32][132]

    const int tid  = threadIdx.x;
    const int p0   = blockIdx.x * 128;
    const int lane = tid & 31, wid = tid >> 5;
    const int wm = wid & 3, wn = wid >> 2;
    const int g4 = lane >> 2, t4 = lane & 3;
    const int l7 = lane & 7, l8 = (lane >> 3) & 1, l16 = lane >> 4;

    // ---- LayerNorm (+ tf32 rounding): 2 threads/position, 64 ch each ----
    {
        int pos = tid >> 1, sub = tid & 1;
        const float* xr = x + (size_t)(p0 + pos) * Cc + sub * 64;
        float4 bufv[16];
        float s = 0.f, sq = 0.f;
        #pragma unroll
        for (int t = 0; t < 16; ++t) {
            bufv[t] = ((const float4*)xr)[t];
            s  += bufv[t].x + bufv[t].y + bufv[t].z + bufv[t].w;
            sq += bufv[t].x*bufv[t].x + bufv[t].y*bufv[t].y
                + bufv[t].z*bufv[t].z + bufv[t].w*bufv[t].w;
        }
        s  += __shfl_xor_sync(0xffffffffu, s, 1);
        sq += __shfl_xor_sync(0xffffffffu, sq, 1);
        float mu   = s * (1.f/128.f);
        float rstd = rsqrtf(sq * (1.f/128.f) - mu*mu + 1e-5f);
        #pragma unroll
        for (int t = 0; t < 16; ++t) {
            int cb = sub*64 + t*4;
            float4 w4 = *(const float4*)(niw + cb);
            float4 b4 = *(const float4*)(nib + cb);
            float4 o;
            o.x = round_tf32((bufv[t].x - mu)*rstd*w4.x + b4.x);
            o.y = round_tf32((bufv[t].y - mu)*rstd*w4.y + b4.y);
            o.z = round_tf32((bufv[t].z - mu)*rstd*w4.z + b4.z);
            o.w = round_tf32((bufv[t].w - mu)*rstd*w4.w + b4.w);
            *(float4*)&xn[pos*XS + cb] = o;
        }
    }
    __syncthreads();

    // ldmatrix lane-address bases (bytes), constant across tiles
    uint32_t aoff[2];
    #pragma unroll
    for (int mt = 0; mt < 2; ++mt) {
        int arow = wm*32 + mt*16 + l7 + l8*8;
        aoff[mt] = smem_u32(&xn[arow*XS + l16*4]);
    }
    const int brow = wn*16 + l16*8 + l7;
    const uint32_t goff = smem_u32(&Wg[brow*XS + l8*4]);
    const uint32_t poff = smem_u32(&Wp[brow*XS + l8*4]);
    const int orow = wn*8 + l7;
    const uint32_t ooff = smem_u32(&Wo[orow*XS + l8*4]);

    // ---- 8 super-tiles: G(32d) + P(32d) + gate(16d) per pass ----
    for (int t = 0; t < 8; ++t) {
        const float* gsrc = giw + (size_t)t*32*Cc;
        const float* psrc = piw + (size_t)t*32*Cc;
        const float* osrc = gow + (size_t)t*16*Cc;
        for (int q = tid; q < 1024; q += 256) {
            int d = q >> 5, c4 = q & 31;
            float4 vg = *(const float4*)(gsrc + d*Cc + c4*4);
            float4 vp = *(const float4*)(psrc + d*Cc + c4*4);
            vg.x = round_tf32(vg.x); vg.y = round_tf32(vg.y);
            vg.z = round_tf32(vg.z); vg.w = round_tf32(vg.w);
            vp.x = round_tf32(vp.x); vp.y = round_tf32(vp.y);
            vp.z = round_tf32(vp.z); vp.w = round_tf32(vp.w);
            *(float4*)&Wg[d*XS + c4*4] = vg;
            *(float4*)&Wp[d*XS + c4*4] = vp;
        }
        for (int q = tid; q < 512; q += 256) {
            int d = q >> 5, c4 = q & 31;
            float4 vo = *(const float4*)(osrc + d*Cc + c4*4);
            vo.x = round_tf32(vo.x); vo.y = round_tf32(vo.y);
            vo.z = round_tf32(vo.z); vo.w = round_tf32(vo.w);
            *(float4*)&Wo[d*XS + c4*4] = vo;
        }
        __syncthreads();

        float accG[2][2][4] = {}, accP[2][2][4] = {}, accO[2][4] = {};
        uint32_t af[2][2][4], bg[2][4], bp[2][4], bo[2][2];
        // prologue: fragments for ks = 0
        ldsm_x4(af[0][0], aoff[0]);
        ldsm_x4(af[0][1], aoff[1]);
        ldsm_x4(bg[0], goff);
        ldsm_x4(bp[0], poff);
        ldsm_x2(bo[0], ooff);
        #pragma unroll
        for (int ks = 0; ks < 16; ++ks) {
            const int cur = ks & 1, nxt = cur ^ 1;
            if (ks < 15) {
                const uint32_t ko = (uint32_t)(ks + 1) * 32;
                ldsm_x4(af[nxt][0], aoff[0] + ko);
                ldsm_x4(af[nxt][1], aoff[1] + ko);
                ldsm_x4(bg[nxt], goff + ko);
                ldsm_x4(bp[nxt], poff + ko);
                ldsm_x2(bo[nxt], ooff + ko);
            }
            #pragma unroll
            for (int mt = 0; mt < 2; ++mt) {
                mma_tf32(accG[mt][0], af[cur][mt], bg[cur]);
                mma_tf32(accG[mt][1], af[cur][mt], bg[cur] + 2);
                mma_tf32(accP[mt][0], af[cur][mt], bp[cur]);
                mma_tf32(accP[mt][1], af[cur][mt], bp[cur] + 2);
                mma_tf32(accO[mt],    af[cur][mt], bo[cur]);
            }
        }
        __syncthreads();

        // pg = P * sigmoid(G), stage transposed [d][pos] (overlay on Wg)
        #pragma unroll
        for (int mt = 0; mt < 2; ++mt)
            #pragma unroll
            for (int nt = 0; nt < 2; ++nt) {
                int row = wm*32 + mt*16 + g4;
                int col = wn*16 + nt*8 + 2*t4;
                ob[col*XS + row]         = accP[mt][nt][0]*sigmoidf_(accG[mt][nt][0]);
                ob[(col+1)*XS + row]     = accP[mt][nt][1]*sigmoidf_(accG[mt][nt][1]);
                ob[col*XS + row + 8]     = accP[mt][nt][2]*sigmoidf_(accG[mt][nt][2]);
                ob[(col+1)*XS + row + 8] = accP[mt][nt][3]*sigmoidf_(accG[mt][nt][3]);
            }
        __syncthreads();

        float* dst = ((t < 4) ? g_a : g_b) + (size_t)((t & 3)*32)*PP + p0;
        for (int q = tid; q < 1024; q += 256) {
            int d = q >> 5, p4 = q & 31;
            float4 v = *(float4*)&ob[d*XS + p4*4];
            v.x = round_tf32(v.x); v.y = round_tf32(v.y);
            v.z = round_tf32(v.z); v.w = round_tf32(v.w);
            *(float4*)(dst + (size_t)d*PP + p4*4) = v;
        }
        #pragma unroll
        for (int mt = 0; mt < 2; ++mt) {
            int row = wm*32 + mt*16 + g4;
            int col = t*16 + wn*8 + 2*t4;
            float2 o0 = { sigmoidf_(accO[mt][0]), sigmoidf_(accO[mt][1]) };
            float2 o1 = { sigmoidf_(accO[mt][2]), sigmoidf_(accO[mt][3]) };
            *(float2*)(g_gate + (size_t)(p0+row)*Cc + col)   = o0;
            *(float2*)(g_gate + (size_t)(p0+row+8)*Cc + col) = o1;
        }
        __syncthreads();
    }
}

// ---------------------------------------------------------------------------
// K2: per-channel tri_c = A_c @ B_c^T — ldmatrix + B-fragment pipelining.
// ---------------------------------------------------------------------------
#define KS2 36
#define K2_BUF (128*KS2)

__global__ __launch_bounds__(256, 2) void k2_trimul_tc()
{
    extern __shared__ float sm2[];
    float* As = sm2;               // [2][128][36]
    float* Bs = sm2 + 2*K2_BUF;    // [2][128][36]

    const int tid = threadIdx.x, lane = tid & 31, wid = tid >> 5;
    const int wm = wid & 3, wn = wid >> 2;
    const int g4 = lane >> 2, t4 = lane & 3;
    const int l7 = lane & 7, l8 = (lane >> 3) & 1, l16 = lane >> 4;
    const int c = blockIdx.z, i0 = blockIdx.y*128, j0 = blockIdx.x*128;
    const float* Ag = g_a + (size_t)c*PP + (size_t)i0*Nn;
    const float* Bg = g_b + (size_t)c*PP + (size_t)j0*Nn;
    const uint32_t sA = smem_u32(As), sB = smem_u32(Bs);

    const int r_ld  = tid >> 3;
    const int c4_ld = tid & 7;

    uint32_t aoff[2];
    #pragma unroll
    for (int mt = 0; mt < 2; ++mt) {
        int arow = wm*32 + mt*16 + l7 + l8*8;
        aoff[mt] = (uint32_t)(arow*KS2 + l16*4) * 4;
    }
    uint32_t boff[4];
    #pragma unroll
    for (int np = 0; np < 4; ++np) {
        int br = wn*64 + np*16 + l16*8 + l7;
        boff[np] = (uint32_t)(br*KS2 + l8*4) * 4;
    }

    float acc[2][8][4] = {};

    #pragma unroll
    for (int q = 0; q < 4; ++q) {
        int r = r_ld + q*32;
        cp16(sA + (uint32_t)(r*KS2 + c4_ld*4)*4, Ag + (size_t)r*Nn + c4_ld*4);
        cp16(sB + (uint32_t)(r*KS2 + c4_ld*4)*4, Bg + (size_t)r*Nn + c4_ld*4);
    }
    CP_COMMIT();

    for (int kt = 0; kt < 16; ++kt) {
        const int buf = kt & 1;
        CP_WAIT0();
        __syncthreads();
        if (kt < 15) {
            const int kk = (kt+1)*32;
            const uint32_t off = (uint32_t)((buf^1)*K2_BUF)*4;
            #pragma unroll
            for (int q = 0; q < 4; ++q) {
                int r = r_ld + q*32;
                cp16(sA + off + (uint32_t)(r*KS2 + c4_ld*4)*4, Ag + (size_t)r*Nn + kk + c4_ld*4);
                cp16(sB + off + (uint32_t)(r*KS2 + c4_ld*4)*4, Bg + (size_t)r*Nn + kk + c4_ld*4);
            }
            CP_COMMIT();
        }
        const uint32_t bufA = sA + (uint32_t)(buf*K2_BUF)*4;
        const uint32_t bufB = sB + (uint32_t)(buf*K2_BUF)*4;

        uint32_t bf[2][4][4];
        #pragma unroll
        for (int np = 0; np < 4; ++np)
            ldsm_x4(bf[0][np], bufB + boff[np]);
        #pragma unroll
        for (int ks = 0; ks < 4; ++ks) {
            const int cur = ks & 1, nxt = cur ^ 1;
            const uint32_t ko = ks*32;
            uint32_t af[2][4];
            ldsm_x4(af[0], bufA + aoff[0] + ko);
            ldsm_x4(af[1], bufA + aoff[1] + ko);
            if (ks < 3) {
                #pragma unroll
                for (int np = 0; np < 4; ++np)
                    ldsm_x4(bf[nxt][np], bufB + boff[np] + ko + 32);
            }
            #pragma unroll
            for (int mt = 0; mt < 2; ++mt)
                #pragma unroll
                for (int np = 0; np < 4; ++np) {
                    mma_tf32(acc[mt][np*2],   af[mt], bf[cur][np]);
                    mma_tf32(acc[mt][np*2+1], af[mt], bf[cur][np] + 2);
                }
        }
        __syncthreads();
    }

    float* Cm = g_tri + (size_t)c*PP;
    #pragma unroll
    for (int mt = 0; mt < 2; ++mt)
        #pragma unroll
        for (int nt = 0; nt < 8; ++nt) {
            int row = i0 + wm*32 + mt*16 + g4;
            int col = j0 + wn*64 + nt*8 + 2*t4;
            float2 o0 = { acc[mt][nt][0], acc[mt][nt][1] };
            float2 o1 = { acc[mt][nt][2], acc[mt][nt][3] };
            *(float2*)(Cm + (size_t)row*Nn + col)     = o0;
            *(float2*)(Cm + (size_t)(row+8)*Nn + col) = o1;
        }
}

// ---------------------------------------------------------------------------
// K3 v2: out = (LN_c(tri) @ p_out_w^T) * gate, j-tile 64, 2 CTAs/SM
// (unchanged from R11/R13).
// ---------------------------------------------------------------------------
#define TS3 68

__global__ __launch_bounds__(256, 2) void k3_out(
    const float* __restrict__ now, const float* __restrict__ nob,
    const float* __restrict__ poww, float* __restrict__ out)
{
    extern __shared__ float sm3[];
    float* ts = sm3;             // [128 c][68]  (64 j cols)
    float* Ws = ts + 128*TS3;    // [128 d][132 k] tf32-rounded

    const int tid  = threadIdx.x;
    const int lane = tid & 31, wid = tid >> 5;
    const int wm = wid & 1, wn = wid >> 1;
    const int g4 = lane >> 2, t4 = lane & 3;
    const int i = blockIdx.y, jb = blockIdx.x;

    for (int q = tid; q < 4096; q += 256) {
        int d = q >> 5, c4 = q & 31;
        float4 v = *(const float4*)(poww + (size_t)d*Cc + c4*4);
        v.x = round_tf32(v.x); v.y = round_tf32(v.y);
        v.z = round_tf32(v.z); v.w = round_tf32(v.w);
        *(float4*)&Ws[d*XS + c4*4] = v;
    }
    const float* tsrc = g_tri + (size_t)i*Nn + jb*64;
    for (int q = tid; q < 2048; q += 256) {
        int c = q >> 4, j4 = q & 15;
        *(float4*)&ts[c*TS3 + j4*4] = *(const float4*)(tsrc + (size_t)c*PP + j4*4);
    }
    __syncthreads();

    {
        int j = tid >> 2, sub = tid & 3;
        float s = 0.f, sq = 0.f;
        #pragma unroll 8
        for (int t = 0; t < 32; ++t) {
            float v = ts[(sub*32 + t)*TS3 + j];
            s += v; sq += v*v;
        }
        s  += __shfl_xor_sync(0xffffffffu, s, 1);
        s  += __shfl_xor_sync(0xffffffffu, s, 2);
        sq += __shfl_xor_sync(0xffffffffu, sq, 1);
        sq += __shfl_xor_sync(0xffffffffu, sq, 2);
        float mu   = s*(1.f/128.f);
        float rstd = rsqrtf(fmaxf(sq*(1.f/128.f) - mu*mu, 0.f) + 1e-5f);
        #pragma unroll 8
        for (int t = 0; t < 32; ++t) {
            int c = sub*32 + t;
            ts[c*TS3 + j] = (ts[c*TS3 + j] - mu)*rstd*now[c] + nob[c];
        }
    }
    __syncthreads();

    float acc[2][4][4] = {};
    #pragma unroll 4
    for (int ks = 0; ks < 16; ++ks) {
        int kb = ks*8;
        uint32_t ah[2][4], al[2][4];
        #pragma unroll
        for (int mt = 0; mt < 2; ++mt) {
            int row = wm*32 + mt*16 + g4;
            split_tf32(ts[(kb + t4)*TS3 + row],       ah[mt][0], al[mt][0]);
            split_tf32(ts[(kb + t4)*TS3 + row + 8],   ah[mt][1], al[mt][1]);
            split_tf32(ts[(kb + t4 + 4)*TS3 + row],   ah[mt][2], al[mt][2]);
            split_tf32(ts[(kb + t4 + 4)*TS3 + row+8], ah[mt][3], al[mt][3]);
        }
        uint32_t bh[4][2];
        #pragma unroll
        for (int nt = 0; nt < 4; ++nt) {
            int dn = wn*32 + nt*8 + g4;
            bh[nt][0] = __float_as_uint(Ws[dn*XS + kb + t4]);
            bh[nt][1] = __float_as_uint(Ws[dn*XS + kb + t4 + 4]);
        }
        #pragma unroll
        for (int mt = 0; mt < 2; ++mt)
            #pragma unroll
            for (int nt = 0; nt < 4; ++nt) {
                mma_tf32(acc[mt][nt], ah[mt], bh[nt]);
                mma_tf32(acc[mt][nt], al[mt], bh[nt]);
            }
    }

    const size_t pbase = (size_t)i*Nn + jb*64;
    #pragma unroll
    for (int mt = 0; mt < 2; ++mt)
        #pragma unroll
        for (int nt = 0; nt < 4; ++nt) {
            int row = wm*32 + mt*16 + g4;
            int col = wn*32 + nt*8 + 2*t4;
            size_t off0 = (pbase + row)*Cc + col;
            size_t off1 = (pbase + row + 8)*Cc + col;
            float2 ga = *(const float2*)(g_gate + off0);
            float2 gb = *(const float2*)(g_gate + off1);
            float2 o0 = { acc[mt][nt][0]*ga.x, acc[mt][nt][1]*ga.y };
            float2 o1 = { acc[mt][nt][2]*gb.x, acc[mt][nt][3]*gb.y };
            *(float2*)(out + off0) = o0;
            *(float2*)(out + off1) = o1;
        }
}

// ---------------------------------------------------------------------------
extern "C" void kernel_launch(void* const* d_in, const int* in_sizes, int n_in,
                              void* d_out, int out_size)
{
    const float* x    = (const float*)d_in[0];
    const float* niw  = (const float*)d_in[1];
    const float* nib  = (const float*)d_in[2];
    const float* giw  = (const float*)d_in[3];
    const float* piw  = (const float*)d_in[4];
    const float* gow  = (const float*)d_in[5];
    const float* now  = (const float*)d_in[6];
    const float* nob  = (const float*)d_in[7];
    const float* poww = (const float*)d_in[8];
    float* out = (float*)d_out;

    const int k1_smem = (128 + 32 + 32 + 16) * XS * 4;  // 109824 B (2 CTAs/SM)
    const int k2_smem = 4 * K2_BUF * 4;                 //  73728 B (2 CTAs/SM)
    const int k3_smem = (128*TS3 + 128*XS) * 4;         // 102400 B (2 CTAs/SM)
    cudaFuncSetAttribute(k1_ln_proj,   cudaFuncAttributeMaxDynamicSharedMemorySize, k1_smem);
    cudaFuncSetAttribute(k2_trimul_tc, cudaFuncAttributeMaxDynamicSharedMemorySize, k2_smem);
    cudaFuncSetAttribute(k3_out,       cudaFuncAttributeMaxDynamicSharedMemorySize, k3_smem);

    k1_ln_proj<<<PP/128, 256, k1_smem>>>(x, niw, nib, giw, piw, gow);
    k2_trimul_tc<<<dim3(4, 4, 128), 256, k2_smem>>>();
    k3_out<<<dim3(8, Nn), 256, k3_smem>>>(now, nob, poww, out);
}

// round 16
// speedup vs baseline: 1.0429x; 1.0429x over previous
#include <cuda_runtime.h>
#include <cstdint>

#define Nn 512
#define Cc 128
#define PP (Nn*Nn)   // 262144 positions

// Scratch (device globals — no allocation allowed in kernel_launch)
__device__ float g_a[(size_t)Cc*PP];     // [c][i][k]  tf32-rounded A operand
__device__ float g_b[(size_t)Cc*PP];     // [c][j][k]  tf32-rounded B operand
__device__ float g_gate[(size_t)PP*Cc];  // [p][c]     sigmoid output gate
__device__ float g_tri[(size_t)Cc*PP];   // [c][i][j]  triangle result

__device__ __forceinline__ float sigmoidf_(float v) {
    return 1.f / (1.f + __expf(-v));
}

// ===================== mma.sync tf32 helpers (sm_80+) ======================
__device__ __forceinline__ uint32_t smem_u32(const void* p) {
    uint32_t a;
    asm("{ .reg .u64 t; cvta.to.shared.u64 t, %1; cvt.u32.u64 %0, t; }"
        : "=r"(a) : "l"(p));
    return a;
}
__device__ __forceinline__ uint32_t cvt_tf32(float f) {
    uint32_t r;
    asm("cvt.rna.tf32.f32 %0, %1;" : "=r"(r) : "f"(f));
    return r;
}
__device__ __forceinline__ float round_tf32(float f) {
    return __uint_as_float(cvt_tf32(f));
}
__device__ __forceinline__ void split_tf32(float f, uint32_t& hi, uint32_t& lo) {
    hi = cvt_tf32(f);
    lo = cvt_tf32(f - __uint_as_float(hi));
}
__device__ __forceinline__ void mma_tf32(float* d, const uint32_t* a, const uint32_t* b) {
    asm volatile(
        "mma.sync.aligned.m16n8k8.row.col.f32.tf32.tf32.f32 "
        "{%0,%1,%2,%3}, {%4,%5,%6,%7}, {%8,%9}, {%0,%1,%2,%3};"
        : "+f"(d[0]), "+f"(d[1]), "+f"(d[2]), "+f"(d[3])
        : "r"(a[0]), "r"(a[1]), "r"(a[2]), "r"(a[3]), "r"(b[0]), "r"(b[1]));
}
__device__ __forceinline__ void ldsm_x4(uint32_t* r, uint32_t addr) {
    asm volatile("ldmatrix.sync.aligned.m8n8.x4.shared.b16 {%0,%1,%2,%3}, [%4];"
        : "=r"(r[0]), "=r"(r[1]), "=r"(r[2]), "=r"(r[3]) : "r"(addr));
}
__device__ __forceinline__ void ldsm_x2(uint32_t* r, uint32_t addr) {
    asm volatile("ldmatrix.sync.aligned.m8n8.x2.shared.b16 {%0,%1}, [%2];"
        : "=r"(r[0]), "=r"(r[1]) : "r"(addr));
}
__device__ __forceinline__ void cp16(uint32_t s, const void* g) {
    asm volatile("cp.async.cg.shared.global [%0], [%1], 16;" :: "r"(s), "l"(g));
}
#define CP_COMMIT() asm volatile("cp.async.commit_group;" ::: "memory")
#define CP_WAIT0()  asm volatile("cp.async.wait_group 0;" ::: "memory")

#define XS 132

// ---------------------------------------------------------------------------
// K1 v6 (R13-proven): LN + fused super-tiles + ldmatrix fragment loads.
// Block = 128 positions, 256 threads (4 pos-warps x 2 d-warps), 2 CTAs/SM.
// ---------------------------------------------------------------------------
__global__ __launch_bounds__(256, 2) void k1_ln_proj(
    const float* __restrict__ x,
    const float* __restrict__ niw, const float* __restrict__ nib,
    const float* __restrict__ giw, const float* __restrict__ piw,
    const float* __restrict__ gow)
{
    extern __shared__ float sm[];
    float* xn = sm;              // [128][132] tf32-rounded LN output
    float* Wg = xn + 128*XS;     // [32][132]
    float* Wp = Wg + 32*XS;      // [32][132]
    float* Wo = Wp + 32*XS;      // [16][132]
    float* ob = Wg;              // pg staging overlay [32][132]

    const int tid  = threadIdx.x;
    const int p0   = blockIdx.x * 128;
    const int lane = tid & 31, wid = tid >> 5;
    const int wm = wid & 3, wn = wid >> 2;
    const int g4 = lane >> 2, t4 = lane & 3;
    const int l7 = lane & 7, l8 = (lane >> 3) & 1, l16 = lane >> 4;

    // ---- LayerNorm (+ tf32 rounding): 2 threads/position, 64 ch each ----
    {
        int pos = tid >> 1, sub = tid & 1;
        const float* xr = x + (size_t)(p0 + pos) * Cc + sub * 64;
        float4 bufv[16];
        float s = 0.f, sq = 0.f;
        #pragma unroll
        for (int t = 0; t < 16; ++t) {
            bufv[t] = ((const float4*)xr)[t];
            s  += bufv[t].x + bufv[t].y + bufv[t].z + bufv[t].w;
            sq += bufv[t].x*bufv[t].x + bufv[t].y*bufv[t].y
                + bufv[t].z*bufv[t].z + bufv[t].w*bufv[t].w;
        }
        s  += __shfl_xor_sync(0xffffffffu, s, 1);
        sq += __shfl_xor_sync(0xffffffffu, sq, 1);
        float mu   = s * (1.f/128.f);
        float rstd = rsqrtf(sq * (1.f/128.f) - mu*mu + 1e-5f);
        #pragma unroll
        for (int t = 0; t < 16; ++t) {
            int cb = sub*64 + t*4;
            float4 w4 = *(const float4*)(niw + cb);
            float4 b4 = *(const float4*)(nib + cb);
            float4 o;
            o.x = round_tf32((bufv[t].x - mu)*rstd*w4.x + b4.x);
            o.y = round_tf32((bufv[t].y - mu)*rstd*w4.y + b4.y);
            o.z = round_tf32((bufv[t].z - mu)*rstd*w4.z + b4.z);
            o.w = round_tf32((bufv[t].w - mu)*rstd*w4.w + b4.w);
            *(float4*)&xn[pos*XS + cb] = o;
        }
    }
    __syncthreads();

    // ldmatrix lane-address bases (bytes), constant across tiles
    uint32_t aoff[2];
    #pragma unroll
    for (int mt = 0; mt < 2; ++mt) {
        int arow = wm*32 + mt*16 + l7 + l8*8;
        aoff[mt] = smem_u32(&xn[arow*XS + l16*4]);
    }
    const int brow = wn*16 + l16*8 + l7;
    const uint32_t goff = smem_u32(&Wg[brow*XS + l8*4]);
    const uint32_t poff = smem_u32(&Wp[brow*XS + l8*4]);
    const int orow = wn*8 + l7;
    const uint32_t ooff = smem_u32(&Wo[orow*XS + l8*4]);

    // ---- 8 super-tiles: G(32d) + P(32d) + gate(16d) per pass ----
    for (int t = 0; t < 8; ++t) {
        const float* gsrc = giw + (size_t)t*32*Cc;
        const float* psrc = piw + (size_t)t*32*Cc;
        const float* osrc = gow + (size_t)t*16*Cc;
        for (int q = tid; q < 1024; q += 256) {
            int d = q >> 5, c4 = q & 31;
            float4 vg = *(const float4*)(gsrc + d*Cc + c4*4);
            float4 vp = *(const float4*)(psrc + d*Cc + c4*4);
            vg.x = round_tf32(vg.x); vg.y = round_tf32(vg.y);
            vg.z = round_tf32(vg.z); vg.w = round_tf32(vg.w);
            vp.x = round_tf32(vp.x); vp.y = round_tf32(vp.y);
            vp.z = round_tf32(vp.z); vp.w = round_tf32(vp.w);
            *(float4*)&Wg[d*XS + c4*4] = vg;
            *(float4*)&Wp[d*XS + c4*4] = vp;
        }
        for (int q = tid; q < 512; q += 256) {
            int d = q >> 5, c4 = q & 31;
            float4 vo = *(const float4*)(osrc + d*Cc + c4*4);
            vo.x = round_tf32(vo.x); vo.y = round_tf32(vo.y);
            vo.z = round_tf32(vo.z); vo.w = round_tf32(vo.w);
            *(float4*)&Wo[d*XS + c4*4] = vo;
        }
        __syncthreads();

        float accG[2][2][4] = {}, accP[2][2][4] = {}, accO[2][4] = {};
        #pragma unroll 4
        for (int ks = 0; ks < 16; ++ks) {
            const uint32_t ko = ks*32;   // 8 floats per k-step
            uint32_t af[2][4];
            ldsm_x4(af[0], aoff[0] + ko);
            ldsm_x4(af[1], aoff[1] + ko);
            uint32_t bg[4], bp[4], bo[2];
            ldsm_x4(bg, goff + ko);
            ldsm_x4(bp, poff + ko);
            ldsm_x2(bo, ooff + ko);
            #pragma unroll
            for (int mt = 0; mt < 2; ++mt) {
                mma_tf32(accG[mt][0], af[mt], bg);
                mma_tf32(accG[mt][1], af[mt], bg + 2);
                mma_tf32(accP[mt][0], af[mt], bp);
                mma_tf32(accP[mt][1], af[mt], bp + 2);
                mma_tf32(accO[mt],    af[mt], bo);
            }
        }
        __syncthreads();

        // pg = P * sigmoid(G), stage transposed [d][pos] (overlay on Wg)
        #pragma unroll
        for (int mt = 0; mt < 2; ++mt)
            #pragma unroll
            for (int nt = 0; nt < 2; ++nt) {
                int row = wm*32 + mt*16 + g4;
                int col = wn*16 + nt*8 + 2*t4;
                ob[col*XS + row]         = accP[mt][nt][0]*sigmoidf_(accG[mt][nt][0]);
                ob[(col+1)*XS + row]     = accP[mt][nt][1]*sigmoidf_(accG[mt][nt][1]);
                ob[col*XS + row + 8]     = accP[mt][nt][2]*sigmoidf_(accG[mt][nt][2]);
                ob[(col+1)*XS + row + 8] = accP[mt][nt][3]*sigmoidf_(accG[mt][nt][3]);
            }
        __syncthreads();

        float* dst = ((t < 4) ? g_a : g_b) + (size_t)((t & 3)*32)*PP + p0;
        for (int q = tid; q < 1024; q += 256) {
            int d = q >> 5, p4 = q & 31;
            float4 v = *(float4*)&ob[d*XS + p4*4];
            v.x = round_tf32(v.x); v.y = round_tf32(v.y);
            v.z = round_tf32(v.z); v.w = round_tf32(v.w);
            *(float4*)(dst + (size_t)d*PP + p4*4) = v;
        }
        #pragma unroll
        for (int mt = 0; mt < 2; ++mt) {
            int row = wm*32 + mt*16 + g4;
            int col = t*16 + wn*8 + 2*t4;
            float2 o0 = { sigmoidf_(accO[mt][0]), sigmoidf_(accO[mt][1]) };
            float2 o1 = { sigmoidf_(accO[mt][2]), sigmoidf_(accO[mt][3]) };
            *(float2*)(g_gate + (size_t)(p0+row)*Cc + col)   = o0;
            *(float2*)(g_gate + (size_t)(p0+row+8)*Cc + col) = o1;
        }
        __syncthreads();
    }
}

// ---------------------------------------------------------------------------
// K2 (R13-proven): per-channel tri_c = A_c @ B_c^T, ldmatrix, 2 CTAs/SM.
// ---------------------------------------------------------------------------
#define KS2 36
#define K2_BUF (128*KS2)

__global__ __launch_bounds__(256, 2) void k2_trimul_tc()
{
    extern __shared__ float sm2[];
    float* As = sm2;               // [2][128][36]
    float* Bs = sm2 + 2*K2_BUF;    // [2][128][36]

    const int tid = threadIdx.x, lane = tid & 31, wid = tid >> 5;
    const int wm = wid & 3, wn = wid >> 2;
    const int g4 = lane >> 2, t4 = lane & 3;
    const int l7 = lane & 7, l8 = (lane >> 3) & 1, l16 = lane >> 4;
    const int c = blockIdx.z, i0 = blockIdx.y*128, j0 = blockIdx.x*128;
    const float* Ag = g_a + (size_t)c*PP + (size_t)i0*Nn;
    const float* Bg = g_b + (size_t)c*PP + (size_t)j0*Nn;
    const uint32_t sA = smem_u32(As), sB = smem_u32(Bs);

    const int r_ld  = tid >> 3;
    const int c4_ld = tid & 7;

    uint32_t aoff[2];
    #pragma unroll
    for (int mt = 0; mt < 2; ++mt) {
        int arow = wm*32 + mt*16 + l7 + l8*8;
        aoff[mt] = (uint32_t)(arow*KS2 + l16*4) * 4;
    }
    uint32_t boff[4];
    #pragma unroll
    for (int np = 0; np < 4; ++np) {
        int br = wn*64 + np*16 + l16*8 + l7;
        boff[np] = (uint32_t)(br*KS2 + l8*4) * 4;
    }

    float acc[2][8][4] = {};

    #pragma unroll
    for (int q = 0; q < 4; ++q) {
        int r = r_ld + q*32;
        cp16(sA + (uint32_t)(r*KS2 + c4_ld*4)*4, Ag + (size_t)r*Nn + c4_ld*4);
        cp16(sB + (uint32_t)(r*KS2 + c4_ld*4)*4, Bg + (size_t)r*Nn + c4_ld*4);
    }
    CP_COMMIT();

    for (int kt = 0; kt < 16; ++kt) {
        const int buf = kt & 1;
        CP_WAIT0();
        __syncthreads();
        if (kt < 15) {
            const int kk = (kt+1)*32;
            const uint32_t off = (uint32_t)((buf^1)*K2_BUF)*4;
            #pragma unroll
            for (int q = 0; q < 4; ++q) {
                int r = r_ld + q*32;
                cp16(sA + off + (uint32_t)(r*KS2 + c4_ld*4)*4, Ag + (size_t)r*Nn + kk + c4_ld*4);
                cp16(sB + off + (uint32_t)(r*KS2 + c4_ld*4)*4, Bg + (size_t)r*Nn + kk + c4_ld*4);
            }
            CP_COMMIT();
        }
        const uint32_t bufA = sA + (uint32_t)(buf*K2_BUF)*4;
        const uint32_t bufB = sB + (uint32_t)(buf*K2_BUF)*4;
        #pragma unroll
        for (int ks = 0; ks < 4; ++ks) {
            const uint32_t ko = ks*32;
            uint32_t af[2][4];
            ldsm_x4(af[0], bufA + aoff[0] + ko);
            ldsm_x4(af[1], bufA + aoff[1] + ko);
            uint32_t bf[4][4];
            #pragma unroll
            for (int np = 0; np < 4; ++np)
                ldsm_x4(bf[np], bufB + boff[np] + ko);
            #pragma unroll
            for (int mt = 0; mt < 2; ++mt)
                #pragma unroll
                for (int np = 0; np < 4; ++np) {
                    mma_tf32(acc[mt][np*2],   af[mt], bf[np]);
                    mma_tf32(acc[mt][np*2+1], af[mt], bf[np] + 2);
                }
        }
        __syncthreads();
    }

    float* Cm = g_tri + (size_t)c*PP;
    #pragma unroll
    for (int mt = 0; mt < 2; ++mt)
        #pragma unroll
        for (int nt = 0; nt < 8; ++nt) {
            int row = i0 + wm*32 + mt*16 + g4;
            int col = j0 + wn*64 + nt*8 + 2*t4;
            float2 o0 = { acc[mt][nt][0], acc[mt][nt][1] };
            float2 o1 = { acc[mt][nt][2], acc[mt][nt][3] };
            *(float2*)(Cm + (size_t)row*Nn + col)     = o0;
            *(float2*)(Cm + (size_t)(row+8)*Nn + col) = o1;
        }
}

// ---------------------------------------------------------------------------
// K3 v4: out = (LN_c(tri) @ p_out_w^T) * gate, j-tile 64.
// Weight matrix processed in TWO 64-d halves (Ws = 64x132 = 33.8 KB) =>
// smem 68.6 KB => 3 CTAs/SM. Numerics identical (d-halves independent).
// Warps: 2 j-warps x 4 d-warps (16 d per half each).
// ---------------------------------------------------------------------------
#define TS3 68

__global__ __launch_bounds__(256, 3) void k3_out(
    const float* __restrict__ now, const float* __restrict__ nob,
    const float* __restrict__ poww, float* __restrict__ out)
{
    extern __shared__ float sm3[];
    float* ts = sm3;             // [128 c][68]  (64 j cols)
    float* Ws = ts + 128*TS3;    // [64 d][132] tf32-rounded (one half)

    const int tid  = threadIdx.x;
    const int lane = tid & 31, wid = tid >> 5;
    const int wm = wid & 1, wn = wid >> 1;   // j-warp (32 rows), d-warp (16 d/half)
    const int g4 = lane >> 2, t4 = lane & 3;
    const int i = blockIdx.y, jb = blockIdx.x;

    // load ts tile + first weight half
    const float* tsrc = g_tri + (size_t)i*Nn + jb*64;
    for (int q = tid; q < 2048; q += 256) {              // 128 c x 16 f4
        int c = q >> 4, j4 = q & 15;
        *(float4*)&ts[c*TS3 + j4*4] = *(const float4*)(tsrc + (size_t)c*PP + j4*4);
    }
    for (int q = tid; q < 2048; q += 256) {              // 64 d x 32 f4
        int d = q >> 5, c4 = q & 31;
        float4 v = *(const float4*)(poww + (size_t)d*Cc + c4*4);
        v.x = round_tf32(v.x); v.y = round_tf32(v.y);
        v.z = round_tf32(v.z); v.w = round_tf32(v.w);
        *(float4*)&Ws[d*XS + c4*4] = v;
    }
    __syncthreads();

    // LN over c, in place: 4 threads per j column (32 channels each)
    {
        int j = tid >> 2, sub = tid & 3;
        float s = 0.f, sq = 0.f;
        #pragma unroll 8
        for (int t = 0; t < 32; ++t) {
            float v = ts[(sub*32 + t)*TS3 + j];
            s += v; sq += v*v;
        }
        s  += __shfl_xor_sync(0xffffffffu, s, 1);
        s  += __shfl_xor_sync(0xffffffffu, s, 2);
        sq += __shfl_xor_sync(0xffffffffu, sq, 1);
        sq += __shfl_xor_sync(0xffffffffu, sq, 2);
        float mu   = s*(1.f/128.f);
        float rstd = rsqrtf(fmaxf(sq*(1.f/128.f) - mu*mu, 0.f) + 1e-5f);
        #pragma unroll 8
        for (int t = 0; t < 32; ++t) {
            int c = sub*32 + t;
            ts[c*TS3 + j] = (ts[c*TS3 + j] - mu)*rstd*now[c] + nob[c];
        }
    }
    __syncthreads();

    for (int hp = 0; hp < 2; ++hp) {
        if (hp == 1) {
            __syncthreads();   // everyone done with half 0 before overwrite
            const float* wsrc = poww + (size_t)64*Cc;
            for (int q = tid; q < 2048; q += 256) {
                int d = q >> 5, c4 = q & 31;
                float4 v = *(const float4*)(wsrc + (size_t)d*Cc + c4*4);
                v.x = round_tf32(v.x); v.y = round_tf32(v.y);
                v.z = round_tf32(v.z); v.w = round_tf32(v.w);
                *(float4*)&Ws[d*XS + c4*4] = v;
            }
            __syncthreads();
        }

        float acc[2][2][4] = {};
        #pragma unroll 4
        for (int ks = 0; ks < 16; ++ks) {
            int kb = ks*8;
            uint32_t ah[2][4], al[2][4];
            #pragma unroll
            for (int mt = 0; mt < 2; ++mt) {
                int row = wm*32 + mt*16 + g4;     // j index (M dim)
                split_tf32(ts[(kb + t4)*TS3 + row],       ah[mt][0], al[mt][0]);
                split_tf32(ts[(kb + t4)*TS3 + row + 8],   ah[mt][1], al[mt][1]);
                split_tf32(ts[(kb + t4 + 4)*TS3 + row],   ah[mt][2], al[mt][2]);
                split_tf32(ts[(kb + t4 + 4)*TS3 + row+8], ah[mt][3], al[mt][3]);
            }
            uint32_t bh[2][2];
            #pragma unroll
            for (int nt = 0; nt < 2; ++nt) {
                int dn = wn*16 + nt*8 + g4;       // local d within half
                bh[nt][0] = __float_as_uint(Ws[dn*XS + kb + t4]);
                bh[nt][1] = __float_as_uint(Ws[dn*XS + kb + t4 + 4]);
            }
            #pragma unroll
            for (int mt = 0; mt < 2; ++mt)
                #pragma unroll
                for (int nt = 0; nt < 2; ++nt) {
                    mma_tf32(acc[mt][nt], ah[mt], bh[nt]);
                    mma_tf32(acc[mt][nt], al[mt], bh[nt]);
                }
        }

        const size_t pbase = (size_t)i*Nn + jb*64;
        #pragma unroll
        for (int mt = 0; mt < 2; ++mt)
            #pragma unroll
            for (int nt = 0; nt < 2; ++nt) {
                int row = wm*32 + mt*16 + g4;
                int col = hp*64 + wn*16 + nt*8 + 2*t4;
                size_t off0 = (pbase + row)*Cc + col;
                size_t off1 = (pbase + row + 8)*Cc + col;
                float2 ga = *(const float2*)(g_gate + off0);
                float2 gb = *(const float2*)(g_gate + off1);
                float2 o0 = { acc[mt][nt][0]*ga.x, acc[mt][nt][1]*ga.y };
                float2 o1 = { acc[mt][nt][2]*gb.x, acc[mt][nt][3]*gb.y };
                *(float2*)(out + off0) = o0;
                *(float2*)(out + off1) = o1;
            }
    }
}

// ---------------------------------------------------------------------------
extern "C" void kernel_launch(void* const* d_in, const int* in_sizes, int n_in,
                              void* d_out, int out_size)
{
    const float* x    = (const float*)d_in[0];
    const float* niw  = (const float*)d_in[1];
    const float* nib  = (const float*)d_in[2];
    const float* giw  = (const float*)d_in[3];
    const float* piw  = (const float*)d_in[4];
    const float* gow  = (const float*)d_in[5];
    const float* now  = (const float*)d_in[6];
    const float* nob  = (const float*)d_in[7];
    const float* poww = (const float*)d_in[8];
    float* out = (float*)d_out;

    const int k1_smem = (128 + 32 + 32 + 16) * XS * 4;  // 109824 B (2 CTAs/SM)
    const int k2_smem = 4 * K2_BUF * 4;                 //  73728 B (2 CTAs/SM)
    const int k3_smem = (128*TS3 + 64*XS) * 4;          //  68608 B (3 CTAs/SM)
    cudaFuncSetAttribute(k1_ln_proj,   cudaFuncAttributeMaxDynamicSharedMemorySize, k1_smem);
    cudaFuncSetAttribute(k2_trimul_tc, cudaFuncAttributeMaxDynamicSharedMemorySize, k2_smem);
    cudaFuncSetAttribute(k3_out,       cudaFuncAttributeMaxDynamicSharedMemorySize, k3_smem);

    k1_ln_proj<<<PP/128, 256, k1_smem>>>(x, niw, nib, giw, piw, gow);
    k2_trimul_tc<<<dim3(4, 4, 128), 256, k2_smem>>>();
    k3_out<<<dim3(8, Nn), 256, k3_smem>>>(now, nob, poww, out);
}

// round 17
// speedup vs baseline: 1.0531x; 1.0097x over previous
#include <cuda_runtime.h>
#include <cstdint>

#define Nn 512
#define Cc 128
#define PP (Nn*Nn)   // 262144 positions

// Scratch (device globals — no allocation allowed in kernel_launch)
__device__ float g_a[(size_t)Cc*PP];     // [c][i][k]  tf32-rounded A operand
__device__ float g_b[(size_t)Cc*PP];     // [c][j][k]  tf32-rounded B operand
__device__ float g_gate[(size_t)PP*Cc];  // [p][c]     sigmoid output gate
__device__ float g_tri[(size_t)Cc*PP];   // [c][i][j]  triangle result
// Pre-rounded (tf32) weights: rows [0,256) g_in | [256,512) p_in |
// [512,640) g_out | [640,768) p_out
__device__ float g_wr[(size_t)768*Cc];

__device__ __forceinline__ float sigmoidf_(float v) {
    return 1.f / (1.f + __expf(-v));
}

// ===================== mma.sync tf32 helpers (sm_80+) ======================
__device__ __forceinline__ uint32_t smem_u32(const void* p) {
    uint32_t a;
    asm("{ .reg .u64 t; cvta.to.shared.u64 t, %1; cvt.u32.u64 %0, t; }"
        : "=r"(a) : "l"(p));
    return a;
}
__device__ __forceinline__ uint32_t cvt_tf32(float f) {
    uint32_t r;
    asm("cvt.rna.tf32.f32 %0, %1;" : "=r"(r) : "f"(f));
    return r;
}
__device__ __forceinline__ float round_tf32(float f) {
    return __uint_as_float(cvt_tf32(f));
}
__device__ __forceinline__ void split_tf32(float f, uint32_t& hi, uint32_t& lo) {
    hi = cvt_tf32(f);
    lo = cvt_tf32(f - __uint_as_float(hi));
}
__device__ __forceinline__ void mma_tf32(float* d, const uint32_t* a, const uint32_t* b) {
    asm volatile(
        "mma.sync.aligned.m16n8k8.row.col.f32.tf32.tf32.f32 "
        "{%0,%1,%2,%3}, {%4,%5,%6,%7}, {%8,%9}, {%0,%1,%2,%3};"
        : "+f"(d[0]), "+f"(d[1]), "+f"(d[2]), "+f"(d[3])
        : "r"(a[0]), "r"(a[1]), "r"(a[2]), "r"(a[3]), "r"(b[0]), "r"(b[1]));
}
__device__ __forceinline__ void ldsm_x4(uint32_t* r, uint32_t addr) {
    asm volatile("ldmatrix.sync.aligned.m8n8.x4.shared.b16 {%0,%1,%2,%3}, [%4];"
        : "=r"(r[0]), "=r"(r[1]), "=r"(r[2]), "=r"(r[3]) : "r"(addr));
}
__device__ __forceinline__ void ldsm_x2(uint32_t* r, uint32_t addr) {
    asm volatile("ldmatrix.sync.aligned.m8n8.x2.shared.b16 {%0,%1}, [%2];"
        : "=r"(r[0]), "=r"(r[1]) : "r"(addr));
}
__device__ __forceinline__ void cp16(uint32_t s, const void* g) {
    asm volatile("cp.async.cg.shared.global [%0], [%1], 16;" :: "r"(s), "l"(g));
}
#define CP_COMMIT() asm volatile("cp.async.commit_group;" ::: "memory")
#define CP_WAIT0()  asm volatile("cp.async.wait_group 0;" ::: "memory")

#define XS 132

// ---------------------------------------------------------------------------
// K0: pre-round all projection weights to tf32 once.
// ---------------------------------------------------------------------------
__global__ void k0_round_w(
    const float* __restrict__ giw, const float* __restrict__ piw,
    const float* __restrict__ gow, const float* __restrict__ poww)
{
    int row = blockIdx.x, q = threadIdx.x;
    const float* src;
    if      (row < 256) src = giw  + (size_t)row*Cc;
    else if (row < 512) src = piw  + (size_t)(row-256)*Cc;
    else if (row < 640) src = gow  + (size_t)(row-512)*Cc;
    else                src = poww + (size_t)(row-640)*Cc;
    g_wr[(size_t)row*Cc + q] = round_tf32(src[q]);
}

// ---------------------------------------------------------------------------
// K1 v8: R13 base + pre-rounded weights + warp-private epilogue (3 syncs/tile).
// Block = 128 positions, 256 threads (4 pos-warps x 2 d-warps), 2 CTAs/SM.
// ---------------------------------------------------------------------------
__global__ __launch_bounds__(256, 2) void k1_ln_proj(
    const float* __restrict__ x,
    const float* __restrict__ niw, const float* __restrict__ nib)
{
    extern __shared__ float sm[];
    float* xn = sm;              // [128][132] tf32-rounded LN output
    float* Wg = xn + 128*XS;     // [32][132]
    float* Wp = Wg + 32*XS;      // [32][132]
    float* Wo = Wp + 32*XS;      // [16][132]
    float* ob = Wg;              // pg staging overlay [32][132]

    const int tid  = threadIdx.x;
    const int p0   = blockIdx.x * 128;
    const int lane = tid & 31, wid = tid >> 5;
    const int wm = wid & 3, wn = wid >> 2;
    const int g4 = lane >> 2, t4 = lane & 3;
    const int l7 = lane & 7, l8 = (lane >> 3) & 1, l16 = lane >> 4;

    // ---- LayerNorm (+ tf32 rounding): 2 threads/position, 64 ch each ----
    {
        int pos = tid >> 1, sub = tid & 1;
        const float* xr = x + (size_t)(p0 + pos) * Cc + sub * 64;
        float4 bufv[16];
        float s = 0.f, sq = 0.f;
        #pragma unroll
        for (int t = 0; t < 16; ++t) {
            bufv[t] = ((const float4*)xr)[t];
            s  += bufv[t].x + bufv[t].y + bufv[t].z + bufv[t].w;
            sq += bufv[t].x*bufv[t].x + bufv[t].y*bufv[t].y
                + bufv[t].z*bufv[t].z + bufv[t].w*bufv[t].w;
        }
        s  += __shfl_xor_sync(0xffffffffu, s, 1);
        sq += __shfl_xor_sync(0xffffffffu, sq, 1);
        float mu   = s * (1.f/128.f);
        float rstd = rsqrtf(sq * (1.f/128.f) - mu*mu + 1e-5f);
        #pragma unroll
        for (int t = 0; t < 16; ++t) {
            int cb = sub*64 + t*4;
            float4 w4 = *(const float4*)(niw + cb);
            float4 b4 = *(const float4*)(nib + cb);
            float4 o;
            o.x = round_tf32((bufv[t].x - mu)*rstd*w4.x + b4.x);
            o.y = round_tf32((bufv[t].y - mu)*rstd*w4.y + b4.y);
            o.z = round_tf32((bufv[t].z - mu)*rstd*w4.z + b4.z);
            o.w = round_tf32((bufv[t].w - mu)*rstd*w4.w + b4.w);
            *(float4*)&xn[pos*XS + cb] = o;
        }
    }
    __syncthreads();

    // ldmatrix lane-address bases (bytes), constant across tiles
    uint32_t aoff[2];
    #pragma unroll
    for (int mt = 0; mt < 2; ++mt) {
        int arow = wm*32 + mt*16 + l7 + l8*8;
        aoff[mt] = smem_u32(&xn[arow*XS + l16*4]);
    }
    const int brow = wn*16 + l16*8 + l7;
    const uint32_t goff = smem_u32(&Wg[brow*XS + l8*4]);
    const uint32_t poff = smem_u32(&Wp[brow*XS + l8*4]);
    const int orow = wn*8 + l7;
    const uint32_t ooff = smem_u32(&Wo[orow*XS + l8*4]);

    // ---- 8 super-tiles: G(32d) + P(32d) + gate(16d) per pass ----
    for (int t = 0; t < 8; ++t) {
        const float* gsrc = g_wr + (size_t)(t*32)*Cc;
        const float* psrc = g_wr + (size_t)(256 + t*32)*Cc;
        const float* osrc = g_wr + (size_t)(512 + t*16)*Cc;
        for (int q = tid; q < 1024; q += 256) {          // 32 rows x 32 f4
            int d = q >> 5, c4 = q & 31;
            *(float4*)&Wg[d*XS + c4*4] = *(const float4*)(gsrc + d*Cc + c4*4);
            *(float4*)&Wp[d*XS + c4*4] = *(const float4*)(psrc + d*Cc + c4*4);
        }
        for (int q = tid; q < 512; q += 256) {           // 16 rows x 32 f4
            int d = q >> 5, c4 = q & 31;
            *(float4*)&Wo[d*XS + c4*4] = *(const float4*)(osrc + d*Cc + c4*4);
        }
        __syncthreads();                                  // (1) weights ready

        float accG[2][2][4] = {}, accP[2][2][4] = {}, accO[2][4] = {};
        #pragma unroll 4
        for (int ks = 0; ks < 16; ++ks) {
            const uint32_t ko = ks*32;   // 8 floats per k-step
            uint32_t af[2][4];
            ldsm_x4(af[0], aoff[0] + ko);
            ldsm_x4(af[1], aoff[1] + ko);
            uint32_t bg[4], bp[4], bo[2];
            ldsm_x4(bg, goff + ko);
            ldsm_x4(bp, poff + ko);
            ldsm_x2(bo, ooff + ko);
            #pragma unroll
            for (int mt = 0; mt < 2; ++mt) {
                mma_tf32(accG[mt][0], af[mt], bg);
                mma_tf32(accG[mt][1], af[mt], bg + 2);
                mma_tf32(accP[mt][0], af[mt], bp);
                mma_tf32(accP[mt][1], af[mt], bp + 2);
                mma_tf32(accO[mt],    af[mt], bo);
            }
        }
        __syncthreads();                                  // (2) Wg reads done

        // pg = P * sigmoid(G): warp-private staging [16d x 32pos] in ob
        #pragma unroll
        for (int mt = 0; mt < 2; ++mt)
            #pragma unroll
            for (int nt = 0; nt < 2; ++nt) {
                int row = wm*32 + mt*16 + g4;
                int col = wn*16 + nt*8 + 2*t4;
                ob[col*XS + row]         = accP[mt][nt][0]*sigmoidf_(accG[mt][nt][0]);
                ob[(col+1)*XS + row]     = accP[mt][nt][1]*sigmoidf_(accG[mt][nt][1]);
                ob[col*XS + row + 8]     = accP[mt][nt][2]*sigmoidf_(accG[mt][nt][2]);
                ob[(col+1)*XS + row + 8] = accP[mt][nt][3]*sigmoidf_(accG[mt][nt][3]);
            }
        __syncwarp();

        // each warp writes its own 16d x 32pos region, coalesced float4
        {
            float* dst = ((t < 4) ? g_a : g_b) + (size_t)((t & 3)*32)*PP
                       + p0 + wm*32;
            const int p4 = lane & 7;
            #pragma unroll
            for (int tt = 0; tt < 4; ++tt) {
                int dl = wn*16 + tt*4 + (lane >> 3);
                float4 v = *(float4*)&ob[dl*XS + wm*32 + p4*4];
                v.x = round_tf32(v.x); v.y = round_tf32(v.y);
                v.z = round_tf32(v.z); v.w = round_tf32(v.w);
                *(float4*)(dst + (size_t)dl*PP + p4*4) = v;
            }
        }
        // gate: direct write from acc
        #pragma unroll
        for (int mt = 0; mt < 2; ++mt) {
            int row = wm*32 + mt*16 + g4;
            int col = t*16 + wn*8 + 2*t4;
            float2 o0 = { sigmoidf_(accO[mt][0]), sigmoidf_(accO[mt][1]) };
            float2 o1 = { sigmoidf_(accO[mt][2]), sigmoidf_(accO[mt][3]) };
            *(float2*)(g_gate + (size_t)(p0+row)*Cc + col)   = o0;
            *(float2*)(g_gate + (size_t)(p0+row+8)*Cc + col) = o1;
        }
        __syncthreads();                                  // (3) ob free
    }
}

// ---------------------------------------------------------------------------
// K2 (R13-proven): per-channel tri_c = A_c @ B_c^T, ldmatrix, 2 CTAs/SM.
// ---------------------------------------------------------------------------
#define KS2 36
#define K2_BUF (128*KS2)

__global__ __launch_bounds__(256, 2) void k2_trimul_tc()
{
    extern __shared__ float sm2[];
    float* As = sm2;               // [2][128][36]
    float* Bs = sm2 + 2*K2_BUF;    // [2][128][36]

    const int tid = threadIdx.x, lane = tid & 31, wid = tid >> 5;
    const int wm = wid & 3, wn = wid >> 2;
    const int g4 = lane >> 2, t4 = lane & 3;
    const int l7 = lane & 7, l8 = (lane >> 3) & 1, l16 = lane >> 4;
    const int c = blockIdx.z, i0 = blockIdx.y*128, j0 = blockIdx.x*128;
    const float* Ag = g_a + (size_t)c*PP + (size_t)i0*Nn;
    const float* Bg = g_b + (size_t)c*PP + (size_t)j0*Nn;
    const uint32_t sA = smem_u32(As), sB = smem_u32(Bs);

    const int r_ld  = tid >> 3;
    const int c4_ld = tid & 7;

    uint32_t aoff[2];
    #pragma unroll
    for (int mt = 0; mt < 2; ++mt) {
        int arow = wm*32 + mt*16 + l7 + l8*8;
        aoff[mt] = (uint32_t)(arow*KS2 + l16*4) * 4;
    }
    uint32_t boff[4];
    #pragma unroll
    for (int np = 0; np < 4; ++np) {
        int br = wn*64 + np*16 + l16*8 + l7;
        boff[np] = (uint32_t)(br*KS2 + l8*4) * 4;
    }

    float acc[2][8][4] = {};

    #pragma unroll
    for (int q = 0; q < 4; ++q) {
        int r = r_ld + q*32;
        cp16(sA + (uint32_t)(r*KS2 + c4_ld*4)*4, Ag + (size_t)r*Nn + c4_ld*4);
        cp16(sB + (uint32_t)(r*KS2 + c4_ld*4)*4, Bg + (size_t)r*Nn + c4_ld*4);
    }
    CP_COMMIT();

    for (int kt = 0; kt < 16; ++kt) {
        const int buf = kt & 1;
        CP_WAIT0();
        __syncthreads();
        if (kt < 15) {
            const int kk = (kt+1)*32;
            const uint32_t off = (uint32_t)((buf^1)*K2_BUF)*4;
            #pragma unroll
            for (int q = 0; q < 4; ++q) {
                int r = r_ld + q*32;
                cp16(sA + off + (uint32_t)(r*KS2 + c4_ld*4)*4, Ag + (size_t)r*Nn + kk + c4_ld*4);
                cp16(sB + off + (uint32_t)(r*KS2 + c4_ld*4)*4, Bg + (size_t)r*Nn + kk + c4_ld*4);
            }
            CP_COMMIT();
        }
        const uint32_t bufA = sA + (uint32_t)(buf*K2_BUF)*4;
        const uint32_t bufB = sB + (uint32_t)(buf*K2_BUF)*4;
        #pragma unroll
        for (int ks = 0; ks < 4; ++ks) {
            const uint32_t ko = ks*32;
            uint32_t af[2][4];
            ldsm_x4(af[0], bufA + aoff[0] + ko);
            ldsm_x4(af[1], bufA + aoff[1] + ko);
            uint32_t bf[4][4];
            #pragma unroll
            for (int np = 0; np < 4; ++np)
                ldsm_x4(bf[np], bufB + boff[np] + ko);
            #pragma unroll
            for (int mt = 0; mt < 2; ++mt)
                #pragma unroll
                for (int np = 0; np < 4; ++np) {
                    mma_tf32(acc[mt][np*2],   af[mt], bf[np]);
                    mma_tf32(acc[mt][np*2+1], af[mt], bf[np] + 2);
                }
        }
        __syncthreads();
    }

    float* Cm = g_tri + (size_t)c*PP;
    #pragma unroll
    for (int mt = 0; mt < 2; ++mt)
        #pragma unroll
        for (int nt = 0; nt < 8; ++nt) {
            int row = i0 + wm*32 + mt*16 + g4;
            int col = j0 + wn*64 + nt*8 + 2*t4;
            float2 o0 = { acc[mt][nt][0], acc[mt][nt][1] };
            float2 o1 = { acc[mt][nt][2], acc[mt][nt][3] };
            *(float2*)(Cm + (size_t)row*Nn + col)     = o0;
            *(float2*)(Cm + (size_t)(row+8)*Nn + col) = o1;
        }
}

// ---------------------------------------------------------------------------
// K3 v4 (R16-proven): j-tile 64, two 64-d weight halves, 3 CTAs/SM.
// Weights now read pre-rounded from g_wr rows 640..767.
// ---------------------------------------------------------------------------
#define TS3 68

__global__ __launch_bounds__(256, 3) void k3_out(
    const float* __restrict__ now, const float* __restrict__ nob,
    float* __restrict__ out)
{
    extern __shared__ float sm3[];
    float* ts = sm3;             // [128 c][68]  (64 j cols)
    float* Ws = ts + 128*TS3;    // [64 d][132] (one half, pre-rounded)

    const int tid  = threadIdx.x;
    const int lane = tid & 31, wid = tid >> 5;
    const int wm = wid & 1, wn = wid >> 1;
    const int g4 = lane >> 2, t4 = lane & 3;
    const int i = blockIdx.y, jb = blockIdx.x;

    const float* tsrc = g_tri + (size_t)i*Nn + jb*64;
    for (int q = tid; q < 2048; q += 256) {
        int c = q >> 4, j4 = q & 15;
        *(float4*)&ts[c*TS3 + j4*4] = *(const float4*)(tsrc + (size_t)c*PP + j4*4);
    }
    const float* w0 = g_wr + (size_t)640*Cc;
    for (int q = tid; q < 2048; q += 256) {
        int d = q >> 5, c4 = q & 31;
        *(float4*)&Ws[d*XS + c4*4] = *(const float4*)(w0 + (size_t)d*Cc + c4*4);
    }
    __syncthreads();

    {
        int j = tid >> 2, sub = tid & 3;
        float s = 0.f, sq = 0.f;
        #pragma unroll 8
        for (int t = 0; t < 32; ++t) {
            float v = ts[(sub*32 + t)*TS3 + j];
            s += v; sq += v*v;
        }
        s  += __shfl_xor_sync(0xffffffffu, s, 1);
        s  += __shfl_xor_sync(0xffffffffu, s, 2);
        sq += __shfl_xor_sync(0xffffffffu, sq, 1);
        sq += __shfl_xor_sync(0xffffffffu, sq, 2);
        float mu   = s*(1.f/128.f);
        float rstd = rsqrtf(fmaxf(sq*(1.f/128.f) - mu*mu, 0.f) + 1e-5f);
        #pragma unroll 8
        for (int t = 0; t < 32; ++t) {
            int c = sub*32 + t;
            ts[c*TS3 + j] = (ts[c*TS3 + j] - mu)*rstd*now[c] + nob[c];
        }
    }
    __syncthreads();

    for (int hp = 0; hp < 2; ++hp) {
        if (hp == 1) {
            __syncthreads();
            const float* w1 = g_wr + (size_t)(640 + 64)*Cc;
            for (int q = tid; q < 2048; q += 256) {
                int d = q >> 5, c4 = q & 31;
                *(float4*)&Ws[d*XS + c4*4] = *(const float4*)(w1 + (size_t)d*Cc + c4*4);
            }
            __syncthreads();
        }

        float acc[2][2][4] = {};
        #pragma unroll 4
        for (int ks = 0; ks < 16; ++ks) {
            int kb = ks*8;
            uint32_t ah[2][4], al[2][4];
            #pragma unroll
            for (int mt = 0; mt < 2; ++mt) {
                int row = wm*32 + mt*16 + g4;
                split_tf32(ts[(kb + t4)*TS3 + row],       ah[mt][0], al[mt][0]);
                split_tf32(ts[(kb + t4)*TS3 + row + 8],   ah[mt][1], al[mt][1]);
                split_tf32(ts[(kb + t4 + 4)*TS3 + row],   ah[mt][2], al[mt][2]);
                split_tf32(ts[(kb + t4 + 4)*TS3 + row+8], ah[mt][3], al[mt][3]);
            }
            uint32_t bh[2][2];
            #pragma unroll
            for (int nt = 0; nt < 2; ++nt) {
                int dn = wn*16 + nt*8 + g4;
                bh[nt][0] = __float_as_uint(Ws[dn*XS + kb + t4]);
                bh[nt][1] = __float_as_uint(Ws[dn*XS + kb + t4 + 4]);
            }
            #pragma unroll
            for (int mt = 0; mt < 2; ++mt)
                #pragma unroll
                for (int nt = 0; nt < 2; ++nt) {
                    mma_tf32(acc[mt][nt], ah[mt], bh[nt]);
                    mma_tf32(acc[mt][nt], al[mt], bh[nt]);
                }
        }

        const size_t pbase = (size_t)i*Nn + jb*64;
        #pragma unroll
        for (int mt = 0; mt < 2; ++mt)
            #pragma unroll
            for (int nt = 0; nt < 2; ++nt) {
                int row = wm*32 + mt*16 + g4;
                int col = hp*64 + wn*16 + nt*8 + 2*t4;
                size_t off0 = (pbase + row)*Cc + col;
                size_t off1 = (pbase + row + 8)*Cc + col;
                float2 ga = *(const float2*)(g_gate + off0);
                float2 gb = *(const float2*)(g_gate + off1);
                float2 o0 = { acc[mt][nt][0]*ga.x, acc[mt][nt][1]*ga.y };
                float2 o1 = { acc[mt][nt][2]*gb.x, acc[mt][nt][3]*gb.y };
                *(float2*)(out + off0) = o0;
                *(float2*)(out + off1) = o1;
            }
    }
}

// ---------------------------------------------------------------------------
extern "C" void kernel_launch(void* const* d_in, const int* in_sizes, int n_in,
                              void* d_out, int out_size)
{
    const float* x    = (const float*)d_in[0];
    const float* niw  = (const float*)d_in[1];
    const float* nib  = (const float*)d_in[2];
    const float* giw  = (const float*)d_in[3];
    const float* piw  = (const float*)d_in[4];
    const float* gow  = (const float*)d_in[5];
    const float* now  = (const float*)d_in[6];
    const float* nob  = (const float*)d_in[7];
    const float* poww = (const float*)d_in[8];
    float* out = (float*)d_out;

    const int k1_smem = (128 + 32 + 32 + 16) * XS * 4;  // 109824 B (2 CTAs/SM)
    const int k2_smem = 4 * K2_BUF * 4;                 //  73728 B (2 CTAs/SM)
    const int k3_smem = (128*TS3 + 64*XS) * 4;          //  68608 B (3 CTAs/SM)
    cudaFuncSetAttribute(k1_ln_proj,   cudaFuncAttributeMaxDynamicSharedMemorySize, k1_smem);
    cudaFuncSetAttribute(k2_trimul_tc, cudaFuncAttributeMaxDynamicSharedMemorySize, k2_smem);
    cudaFuncSetAttribute(k3_out,       cudaFuncAttributeMaxDynamicSharedMemorySize, k3_smem);

    k0_round_w<<<768, 128>>>(giw, piw, gow, poww);
    k1_ln_proj<<<PP/128, 256, k1_smem>>>(x, niw, nib);
    k2_trimul_tc<<<dim3(4, 4, 128), 256, k2_smem>>>();
    k3_out<<<dim3(8, Nn), 256, k3_smem>>>(now, nob, out);
}